// round 15
// baseline (speedup 1.0000x reference)
#include <cuda_runtime.h>
#include <math.h>

#define NMOL 16
#define NATOM 64
#define RADF 64
#define ANGF 320
#define FEAT 384
#define RCR 5.2f
#define RCA 3.5f
#define FULL 0xffffffffu
#define TPB 256

__constant__ int c_triu16[16] = {
    0,1,2,3,
    1,4,5,6,
    2,5,7,8,
    3,6,8,9
};
// 0.5*cos / 0.5*sin of SHF_Z[z] = pi/16*(1+2z)
__constant__ float c_hcz[8] = {
     0.490392640201615224f,  0.415734806151272618f,  0.277785116509801112f,
     0.097545161008064134f, -0.097545161008064134f, -0.277785116509801112f,
    -0.415734806151272618f, -0.490392640201615224f
};
__constant__ float c_hsz[8] = {
     0.097545161008064134f,  0.277785116509801112f,  0.415734806151272618f,
     0.490392640201615224f,  0.490392640201615224f,  0.415734806151272618f,
     0.277785116509801112f,  0.097545161008064134f
};

__device__ __forceinline__ float pow32(float u) {
    u = fmaxf(u, 0.0f);
    u = u * u; u = u * u; u = u * u; u = u * u; u = u * u;
    return u;
}

// closed-form unordered-pair decode (validated R10/R11/R13)
__device__ __forceinline__ void decode_pair(int p, int npairs, int m_a,
                                            int& jj, int& kk) {
    const int t_ = npairs - 1 - p;
    int K = (int)((__fsqrt_rn((float)(8 * t_ + 1)) - 1.0f) * 0.5f);
    K += ((K + 1) * (K + 2) / 2 <= t_) ? 1 : 0;
    K -= (K * (K + 1) / 2 > t_) ? 1 : 0;
    jj = m_a - 2 - K;
    kk = m_a - 1 - (t_ - K * (K + 1) / 2);
}

__global__ __launch_bounds__(TPB, 8)
void aev_kernel(const int* __restrict__ species,
                const float* __restrict__ coords,
                float* __restrict__ out,
                int aev_base, int write_species)
{
    const int atom = blockIdx.x;          // 0..1023
    const int n = atom >> 6;
    const int i = atom & 63;
    const int tid  = threadIdx.x;
    const int lane = tid & 31;
    const int w    = tid >> 5;

    __shared__ float4 sP[NATOM];          // dx,dy,dz,d               (angular)
    __shared__ float4 sQ[NATOM];          // rinv, sqrt2*fca, spec, - (angular)
    __shared__ float4 sRt[NATOM];         // dense radial: d, wgt(0 if invalid), spec, -
    __shared__ float  s_ang[ANGF];        // angular accumulators

    // zero angular accumulators (all warps, fully parallel)
    if (tid < ANGF) s_ang[tid] = 0.0f;
    if (tid < ANGF - TPB) s_ang[tid + TPB] = 0.0f;

    // ===== prologue: all warps compute geometry; role-split writes =====
    const float* cb = coords + (size_t)n * NATOM * 3;
    const float xi = __ldg(cb + 3 * i);
    const float yi = __ldg(cb + 3 * i + 1);
    const float zi = __ldg(cb + 3 * i + 2);
    const unsigned lt = (1u << lane) - 1u;

    int m_a = 0;
    #pragma unroll
    for (int h = 0; h < 2; h++) {
        const int j = lane + h * 32;
        const float dx = cb[j * 3 + 0] - xi;
        const float dy = cb[j * 3 + 1] - yi;
        const float dz = cb[j * 3 + 2] - zi;
        const float d2 = fmaxf(dx * dx + dy * dy + dz * dz, 1e-20f);
        const float rinv = rsqrtf(d2);
        const float d = d2 * rinv;

        const bool self = (j == i);
        const bool vA = !self && (d <= RCA);
        const unsigned mA = __ballot_sync(FULL, vA);

        if (w == 0) {
            // dense radial table: weight 0 for self / out-of-cutoff entries
            const bool vR = !self && (d <= RCR);
            const float wgt = vR
                ? 0.25f * (0.5f * __cosf((float)M_PI / RCR * d) + 0.5f) : 0.0f;
            sRt[j] = make_float4(d, wgt,
                                 __int_as_float(species[n * NATOM + j]), 0.f);
        } else if (w == 1) {
            if (vA) sP[m_a + __popc(mA & lt)] = make_float4(dx, dy, dz, d);
        } else if (w == 2) {
            if (vA) {
                const float fca = 0.5f * __cosf((float)M_PI / RCA * d) + 0.5f;
                sQ[m_a + __popc(mA & lt)]
                    = make_float4(rinv, 1.41421356237f * fca,
                                  __int_as_float(species[n * NATOM + j]), 0.f);
            }
        }
        m_a += __popc(mA);
    }
    if (write_species && tid == 0) out[atom] = (float)species[n * NATOM + i];
    __syncthreads();                      // lists + dense table + zeroed s_ang

    float* ob = out + aev_base + (size_t)atom * FEAT;

    // ===== radial: dense loop + in-warp butterfly reduce, no partial smem =====
    {
        const int g = tid & 15;           // group (lane-minor -> bfly within warp)
        const int r = tid >> 4;           // radial feature 0..15
        const float shf = 0.9f + 0.26875f * (float)r;
        float a0 = 0.f, a1 = 0.f, a2 = 0.f, a3 = 0.f;
        #pragma unroll
        for (int k = 0; k < 4; k++) {
            const float4 e = sRt[g + 16 * k];
            const int s = __float_as_int(e.z);
            const float t = e.x - shf;
            const float v = __expf(-16.0f * t * t) * e.y;   // e.y==0 kills invalid
            a0 += (s == 0) ? v : 0.f;
            a1 += (s == 1) ? v : 0.f;
            a2 += (s == 2) ? v : 0.f;
            a3 += (s == 3) ? v : 0.f;
        }
        #pragma unroll
        for (int m = 8; m; m >>= 1) {
            a0 += __shfl_xor_sync(FULL, a0, m);
            a1 += __shfl_xor_sync(FULL, a1, m);
            a2 += __shfl_xor_sync(FULL, a2, m);
            a3 += __shfl_xor_sync(FULL, a3, m);
        }
        if (g < 4) {
            const float val = (g == 0) ? a0 : (g == 1) ? a1 : (g == 2) ? a2 : a3;
            ob[g * 16 + r] = val;
        }
    }

    // ===== angular: warp-per-pair, lane = (a,z) feature (R13-validated) =====
    {
        const float sha = 0.9f + 0.65f * (float)(lane >> 3);
        const float hcz = c_hcz[lane & 7], hsz = c_hsz[lane & 7];
        const int npairs = m_a * (m_a - 1) / 2;
        for (int p = w; p < npairs; p += 8) {
            int jj, kk;
            decode_pair(p, npairs, m_a, jj, kk);
            const float4 Pj = sP[jj], Qj = sQ[jj];
            const float4 Pk = sP[kk], Qk = sQ[kk];
            const int pidx = c_triu16[__float_as_int(Qj.z) * 4 + __float_as_int(Qk.z)];

            float c = 0.95f * (Pj.x*Pk.x + Pj.y*Pk.y + Pj.z*Pk.z) * Qj.x * Qk.x;
            c = fminf(0.95f, fmaxf(-0.95f, c));
            const float s = sqrtf(1.0f - c * c);
            const float t2 = 0.5f * (Pj.w + Pk.w) - sha;
            const float f2 = __expf(-8.0f * t2 * t2);
            const float f1 = pow32(fmaf(c, hcz, fmaf(s, hsz, 0.5f)));
            atomicAdd(&s_ang[pidx * 32 + lane], Qj.y * Qk.y * f2 * f1);
        }
    }
    __syncthreads();

    // ===== epilogue: store angular =====
    for (int f = tid; f < ANGF; f += TPB) ob[RADF + f] = s_ang[f];
}

extern "C" void kernel_launch(void* const* d_in, const int* in_sizes, int n_in,
                              void* d_out, int out_size)
{
    const int*   species = (const int*)d_in[0];
    const float* coords  = (const float*)d_in[1];
    float* out = (float*)d_out;

    const int total_atoms = NMOL * NATOM;       // 1024
    int aev_base = 0, write_species = 0;
    if (out_size >= total_atoms * FEAT + total_atoms) {
        aev_base = total_atoms;
        write_species = 1;
    }

    aev_kernel<<<total_atoms, TPB>>>(species, coords, out, aev_base, write_species);
}

// round 16
// speedup vs baseline: 1.1018x; 1.1018x over previous
#include <cuda_runtime.h>
#include <math.h>

#define NMOL 16
#define NATOM 64
#define RADF 64
#define ANGF 320
#define FEAT 384
#define RCR 5.2f
#define RCA 3.5f
#define FULL 0xffffffffu
#define TPB 256

__constant__ int c_triu16[16] = {
    0,1,2,3,
    1,4,5,6,
    2,5,7,8,
    3,6,8,9
};
// 0.5*cos / 0.5*sin of SHF_Z[z] = pi/16*(1+2z)
__constant__ float c_hcz[8] = {
     0.490392640201615224f,  0.415734806151272618f,  0.277785116509801112f,
     0.097545161008064134f, -0.097545161008064134f, -0.277785116509801112f,
    -0.415734806151272618f, -0.490392640201615224f
};
__constant__ float c_hsz[8] = {
     0.097545161008064134f,  0.277785116509801112f,  0.415734806151272618f,
     0.490392640201615224f,  0.490392640201615224f,  0.415734806151272618f,
     0.277785116509801112f,  0.097545161008064134f
};

__device__ __forceinline__ float pow32(float u) {
    u = fmaxf(u, 0.0f);
    u = u * u; u = u * u; u = u * u; u = u * u; u = u * u;
    return u;
}

__global__ __launch_bounds__(TPB, 8)
void aev_kernel(const int* __restrict__ species,
                const float* __restrict__ coords,
                float* __restrict__ out,
                int aev_base, int write_species)
{
    const int atom = blockIdx.x;          // 0..1023
    const int n = atom >> 6;
    const int i = atom & 63;
    const int tid  = threadIdx.x;
    const int lane = tid & 31;
    const int w    = tid >> 5;

    __shared__ float4 sP[NATOM];          // dx,dy,dz,d               (angular)
    __shared__ float4 sQ[NATOM];          // rinv, sqrt2*fca, spec, - (angular)
    __shared__ float4 sR[NATOM];          // d, 0.25*fcr, spec, -     (radial)
    __shared__ float  s_ang[ANGF];        // angular accumulators
    __shared__ float  pR[16 * 68];        // radial partials (pitch 68)
    __shared__ int    sM[2];              // m_r, m_a

    const float* cb = coords + (size_t)n * NATOM * 3;
    const unsigned lt = (1u << lane) - 1u;

    // ===== role-specialized prologue: only warps 0/1/2 compute geometry =====
    if (w < 3) {
        const float xi = __ldg(cb + 3 * i);
        const float yi = __ldg(cb + 3 * i + 1);
        const float zi = __ldg(cb + 3 * i + 2);
        int cnt = 0;
        #pragma unroll
        for (int h = 0; h < 2; h++) {
            const int j = lane + h * 32;
            const float dx = cb[j * 3 + 0] - xi;
            const float dy = cb[j * 3 + 1] - yi;
            const float dz = cb[j * 3 + 2] - zi;
            const float d2 = fmaxf(dx * dx + dy * dy + dz * dz, 1e-20f);
            const float rinv = rsqrtf(d2);
            const float d = d2 * rinv;
            const bool self = (j == i);

            if (w == 0) {
                const bool vR = !self && (d <= RCR);
                const unsigned mR = __ballot_sync(FULL, vR);
                if (vR) {
                    const float hr = 0.25f * (0.5f * __cosf((float)M_PI / RCR * d) + 0.5f);
                    sR[cnt + __popc(mR & lt)]
                        = make_float4(d, hr, __int_as_float(species[n * NATOM + j]), 0.f);
                }
                cnt += __popc(mR);
            } else if (w == 1) {
                const bool vA = !self && (d <= RCA);
                const unsigned mA = __ballot_sync(FULL, vA);
                if (vA) sP[cnt + __popc(mA & lt)] = make_float4(dx, dy, dz, d);
                cnt += __popc(mA);
            } else {
                const bool vA = !self && (d <= RCA);
                const unsigned mA = __ballot_sync(FULL, vA);
                if (vA) {
                    const float fca = 0.5f * __cosf((float)M_PI / RCA * d) + 0.5f;
                    sQ[cnt + __popc(mA & lt)]
                        = make_float4(rinv, 1.41421356237f * fca,
                                      __int_as_float(species[n * NATOM + j]), 0.f);
                }
                cnt += __popc(mA);
            }
        }
        if (lane == 0 && w < 2) sM[w] = cnt;        // w0 -> m_r, w1 -> m_a
        if (w == 0 && lane == 0 && write_species)
            out[atom] = (float)species[n * NATOM + i];
    } else {
        // warps 3-7: zero angular accumulators (160 threads, 2 strided passes)
        const int t0 = tid - 96;
        s_ang[t0] = 0.0f;
        if (t0 + 160 < ANGF) s_ang[t0 + 160] = 0.0f;
    }
    __syncthreads();

    const int m_r = sM[0];
    const int m_a = sM[1];

    // ===== radial: register accum, no atomics (R13-validated) =====
    {
        const int r = tid & 15;
        const int g = tid >> 4;           // 0..15
        const float shf = 0.9f + 0.26875f * (float)r;
        float a0 = 0.f, a1 = 0.f, a2 = 0.f, a3 = 0.f;
        for (int q = g; q < m_r; q += 16) {
            const float4 e = sR[q];
            const int s = __float_as_int(e.z);
            const float t = e.x - shf;
            const float v = __expf(-16.0f * t * t) * e.y;
            a0 += (s == 0) ? v : 0.f;
            a1 += (s == 1) ? v : 0.f;
            a2 += (s == 2) ? v : 0.f;
            a3 += (s == 3) ? v : 0.f;
        }
        pR[g * 68 +  0 + r] = a0;
        pR[g * 68 + 16 + r] = a1;
        pR[g * 68 + 32 + r] = a2;
        pR[g * 68 + 48 + r] = a3;
    }

    // ===== angular: warp-per-pair, incremental natural-order walk =====
    {
        const float sha = 0.9f + 0.65f * (float)(lane >> 3);
        const float hcz = c_hcz[lane & 7], hsz = c_hsz[lane & 7];
        const int npairs = m_a * (m_a - 1) / 2;

        int p = w;
        if (p < npairs) {
            // initial natural-order decode (once per warp, uniform)
            int jj = 0, rem = p;
            while (rem >= m_a - 1 - jj) { rem -= m_a - 1 - jj; jj++; }
            int kk = jj + 1 + rem;

            while (true) {
                const float4 Pj = sP[jj], Qj = sQ[jj];
                const float4 Pk = sP[kk], Qk = sQ[kk];
                const int pidx = c_triu16[__float_as_int(Qj.z) * 4 +
                                          __float_as_int(Qk.z)];

                float c = 0.95f * (Pj.x*Pk.x + Pj.y*Pk.y + Pj.z*Pk.z) * Qj.x * Qk.x;
                c = fminf(0.95f, fmaxf(-0.95f, c));
                const float s = sqrtf(1.0f - c * c);
                const float t2 = 0.5f * (Pj.w + Pk.w) - sha;
                const float f2 = __expf(-8.0f * t2 * t2);
                const float f1 = pow32(fmaf(c, hcz, fmaf(s, hsz, 0.5f)));
                atomicAdd(&s_ang[pidx * 32 + lane], Qj.y * Qk.y * f2 * f1);

                p += 8;
                if (p >= npairs) break;
                // incremental advance in natural row-major order (uniform)
                kk += 8;
                while (kk >= m_a) { const int over = kk - m_a; jj++; kk = jj + 1 + over; }
            }
        }
    }
    __syncthreads();

    // ===== epilogue: reduce radial partials + store =====
    float* ob = out + aev_base + (size_t)atom * FEAT;
    if (tid < RADF) {
        float sum = 0.f;
        #pragma unroll
        for (int g = 0; g < 16; g++) sum += pR[g * 68 + tid];
        ob[tid] = sum;
    }
    for (int f = tid; f < ANGF; f += TPB) ob[RADF + f] = s_ang[f];
}

extern "C" void kernel_launch(void* const* d_in, const int* in_sizes, int n_in,
                              void* d_out, int out_size)
{
    const int*   species = (const int*)d_in[0];
    const float* coords  = (const float*)d_in[1];
    float* out = (float*)d_out;

    const int total_atoms = NMOL * NATOM;       // 1024
    int aev_base = 0, write_species = 0;
    if (out_size >= total_atoms * FEAT + total_atoms) {
        aev_base = total_atoms;
        write_species = 1;
    }

    aev_kernel<<<total_atoms, TPB>>>(species, coords, out, aev_base, write_species);
}

// round 17
// speedup vs baseline: 1.1646x; 1.0570x over previous
#include <cuda_runtime.h>
#include <math.h>

#define NMOL 16
#define NATOM 64
#define RADF 64
#define ANGF 320
#define FEAT 384
#define RCR 5.2f
#define RCA 3.5f
#define FULL 0xffffffffu
#define TPB 256
#define NWARP 8

__constant__ int c_triu16[16] = {
    0,1,2,3,
    1,4,5,6,
    2,5,7,8,
    3,6,8,9
};
// 0.5*cos / 0.5*sin of SHF_Z[z] = pi/16*(1+2z)
__constant__ float c_hcz[8] = {
     0.490392640201615224f,  0.415734806151272618f,  0.277785116509801112f,
     0.097545161008064134f, -0.097545161008064134f, -0.277785116509801112f,
    -0.415734806151272618f, -0.490392640201615224f
};
__constant__ float c_hsz[8] = {
     0.097545161008064134f,  0.277785116509801112f,  0.415734806151272618f,
     0.490392640201615224f,  0.490392640201615224f,  0.415734806151272618f,
     0.277785116509801112f,  0.097545161008064134f
};

__device__ __forceinline__ float pow32(float u) {
    u = fmaxf(u, 0.0f);
    u = u * u; u = u * u; u = u * u; u = u * u; u = u * u;
    return u;
}

__global__ __launch_bounds__(TPB, 8)
void aev_kernel(const int* __restrict__ species,
                const float* __restrict__ coords,
                float* __restrict__ out,
                int aev_base, int write_species)
{
    const int atom = blockIdx.x;          // 0..1023
    const int n = atom >> 6;
    const int i = atom & 63;
    const int tid  = threadIdx.x;
    const int lane = tid & 31;
    const int w    = tid >> 5;

    __shared__ float4 sP[NATOM];          // dx,dy,dz,d               (angular)
    __shared__ float4 sQ[NATOM];          // rinv, sqrt2*fca, spec, - (angular)
    __shared__ float4 sR[NATOM];          // d, 0.25*fcr, spec, -     (radial)
    __shared__ float  pA[NWARP][ANGF];    // per-warp angular partials (no atomics)
    __shared__ float  pR[16 * 68];        // radial partials (pitch 68)
    __shared__ int    sM[2];              // m_r, m_a

    const float* cb = coords + (size_t)n * NATOM * 3;
    const unsigned lt = (1u << lane) - 1u;

    // every warp zeroes ITS OWN angular buffer (warp-private, no cross deps)
    #pragma unroll
    for (int t = 0; t < 10; t++) pA[w][t * 32 + lane] = 0.0f;

    // ===== role-specialized prologue: only warps 0/1/2 compute geometry =====
    if (w < 3) {
        const float xi = __ldg(cb + 3 * i);
        const float yi = __ldg(cb + 3 * i + 1);
        const float zi = __ldg(cb + 3 * i + 2);
        int cnt = 0;
        #pragma unroll
        for (int h = 0; h < 2; h++) {
            const int j = lane + h * 32;
            const float dx = cb[j * 3 + 0] - xi;
            const float dy = cb[j * 3 + 1] - yi;
            const float dz = cb[j * 3 + 2] - zi;
            const float d2 = fmaxf(dx * dx + dy * dy + dz * dz, 1e-20f);
            const float rinv = rsqrtf(d2);
            const float d = d2 * rinv;
            const bool self = (j == i);

            if (w == 0) {
                const bool vR = !self && (d <= RCR);
                const unsigned mR = __ballot_sync(FULL, vR);
                if (vR) {
                    const float hr = 0.25f * (0.5f * __cosf((float)M_PI / RCR * d) + 0.5f);
                    sR[cnt + __popc(mR & lt)]
                        = make_float4(d, hr, __int_as_float(species[n * NATOM + j]), 0.f);
                }
                cnt += __popc(mR);
            } else if (w == 1) {
                const bool vA = !self && (d <= RCA);
                const unsigned mA = __ballot_sync(FULL, vA);
                if (vA) sP[cnt + __popc(mA & lt)] = make_float4(dx, dy, dz, d);
                cnt += __popc(mA);
            } else {
                const bool vA = !self && (d <= RCA);
                const unsigned mA = __ballot_sync(FULL, vA);
                if (vA) {
                    const float fca = 0.5f * __cosf((float)M_PI / RCA * d) + 0.5f;
                    sQ[cnt + __popc(mA & lt)]
                        = make_float4(rinv, 1.41421356237f * fca,
                                      __int_as_float(species[n * NATOM + j]), 0.f);
                }
                cnt += __popc(mA);
            }
        }
        if (lane == 0 && w < 2) sM[w] = cnt;        // w0 -> m_r, w1 -> m_a
        if (w == 0 && lane == 0 && write_species)
            out[atom] = (float)species[n * NATOM + i];
    }
    __syncthreads();

    const int m_r = sM[0];
    const int m_a = sM[1];

    // ===== radial: register accum, no atomics (R13/R16-validated) =====
    {
        const int r = tid & 15;
        const int g = tid >> 4;           // 0..15
        const float shf = 0.9f + 0.26875f * (float)r;
        float a0 = 0.f, a1 = 0.f, a2 = 0.f, a3 = 0.f;
        for (int q = g; q < m_r; q += 16) {
            const float4 e = sR[q];
            const int s = __float_as_int(e.z);
            const float t = e.x - shf;
            const float v = __expf(-16.0f * t * t) * e.y;
            a0 += (s == 0) ? v : 0.f;
            a1 += (s == 1) ? v : 0.f;
            a2 += (s == 2) ? v : 0.f;
            a3 += (s == 3) ? v : 0.f;
        }
        pR[g * 68 +  0 + r] = a0;
        pR[g * 68 + 16 + r] = a1;
        pR[g * 68 + 32 + r] = a2;
        pR[g * 68 + 48 + r] = a3;
    }

    // ===== angular: warp-per-pair, warp-private buffer, NO atomics =====
    {
        const float sha = 0.9f + 0.65f * (float)(lane >> 3);
        const float hcz = c_hcz[lane & 7], hsz = c_hsz[lane & 7];
        const int npairs = m_a * (m_a - 1) / 2;
        float* buf = &pA[w][0];

        int p = w;
        if (p < npairs) {
            // initial natural-order decode (once per warp, uniform)
            int jj = 0, rem = p;
            while (rem >= m_a - 1 - jj) { rem -= m_a - 1 - jj; jj++; }
            int kk = jj + 1 + rem;

            while (true) {
                const float4 Pj = sP[jj], Qj = sQ[jj];
                const float4 Pk = sP[kk], Qk = sQ[kk];
                const int pidx = c_triu16[__float_as_int(Qj.z) * 4 +
                                          __float_as_int(Qk.z)];

                float c = 0.95f * (Pj.x*Pk.x + Pj.y*Pk.y + Pj.z*Pk.z) * Qj.x * Qk.x;
                c = fminf(0.95f, fmaxf(-0.95f, c));
                const float s = sqrtf(1.0f - c * c);
                const float t2 = 0.5f * (Pj.w + Pk.w) - sha;
                const float f2 = __expf(-8.0f * t2 * t2);
                const float f1 = pow32(fmaf(c, hcz, fmaf(s, hsz, 0.5f)));
                buf[pidx * 32 + lane] += Qj.y * Qk.y * f2 * f1;   // plain LDS/STS RMW

                p += 8;
                if (p >= npairs) break;
                kk += 8;
                while (kk >= m_a) { const int over = kk - m_a; jj++; kk = jj + 1 + over; }
            }
        }
    }
    __syncthreads();

    // ===== epilogue: reduce radial + angular partials, store =====
    float* ob = out + aev_base + (size_t)atom * FEAT;
    if (tid < RADF) {
        float sum = 0.f;
        #pragma unroll
        for (int g = 0; g < 16; g++) sum += pR[g * 68 + tid];
        ob[tid] = sum;
    }
    for (int f = tid; f < ANGF; f += TPB) {
        float sum = 0.f;
        #pragma unroll
        for (int b = 0; b < NWARP; b++) sum += pA[b][f];
        ob[RADF + f] = sum;
    }
}

extern "C" void kernel_launch(void* const* d_in, const int* in_sizes, int n_in,
                              void* d_out, int out_size)
{
    const int*   species = (const int*)d_in[0];
    const float* coords  = (const float*)d_in[1];
    float* out = (float*)d_out;

    const int total_atoms = NMOL * NATOM;       // 1024
    int aev_base = 0, write_species = 0;
    if (out_size >= total_atoms * FEAT + total_atoms) {
        aev_base = total_atoms;
        write_species = 1;
    }

    aev_kernel<<<total_atoms, TPB>>>(species, coords, out, aev_base, write_species);
}